// round 11
// baseline (speedup 1.0000x reference)
#include <cuda_runtime.h>
#include <cuda_fp16.h>
#include <cstdint>

// ---------------- problem constants ----------------
#define M_TOT 8192        // B*S = 4*2048
#define N_TOT 4096        // OUT
#define K_TOT 4096        // IN

// ---------------- GEMM tiling: 2 CTAs/SM, classic HMMA path ----------------
#define BM 128
#define BN 128
#define BK 64                    // K halves per stage (128 B of K per row)
#define BKP 72                   // padded row stride in halves (144 B) — conflict-free ldmatrix
#define STAGES 3
#define NIT (K_TOT / BK)         // 64 main-loop iterations
#define THREADS 256              // 8 warps: 2 (M) x 4 (N), warp tile 64x32

#define A_STAGE_H (BM * BKP)     // 9216 halves
#define B_STAGE_H (BN * BKP)     // 9216 halves
#define STG_BYTES ((A_STAGE_H + B_STAGE_H) * 2)   // 36864 B per stage
#define OFF_PARAM (STAGES * STG_BYTES)            // 110592
#define DYN_SMEM (OFF_PARAM + 3 * BN * 4 + BM * 4)  // 112640 -> 2 CTAs ~ 220KB/SM

// ---------------- scratch (device globals: no allocation allowed) ----------------
__device__ __half g_Xh[(size_t)M_TOT * K_TOT];   // 64 MB fp16 input
__device__ __half g_Wh[(size_t)N_TOT * K_TOT];   // 32 MB fp16 weight (exact int8)
__device__ float  g_rowsum[M_TOT];

// ---------------- PTX helpers (sm_80-era, valid on sm_103 baseline) --------
__device__ __forceinline__ uint32_t smem_u32(const void* p) {
    uint32_t a;
    asm("{ .reg .u64 t; cvta.to.shared.u64 t, %1; cvt.u32.u64 %0, t; }" : "=r"(a) : "l"(p));
    return a;
}

__device__ __forceinline__ void cp16(uint32_t dst, const void* src) {
    asm volatile("cp.async.cg.shared.global [%0], [%1], 16;" :: "r"(dst), "l"(src));
}
__device__ __forceinline__ void cp_commit() {
    asm volatile("cp.async.commit_group;" ::: "memory");
}
#define CP_WAIT_GROUP(n) asm volatile("cp.async.wait_group %0;" :: "n"(n) : "memory")

__device__ __forceinline__ void ldsm4(uint32_t& r0, uint32_t& r1, uint32_t& r2, uint32_t& r3,
                                      uint32_t addr) {
    asm volatile("ldmatrix.sync.aligned.m8n8.x4.shared.b16 {%0,%1,%2,%3}, [%4];"
                 : "=r"(r0), "=r"(r1), "=r"(r2), "=r"(r3) : "r"(addr));
}

__device__ __forceinline__ void mma16816(float* c,
                                         uint32_t a0, uint32_t a1, uint32_t a2, uint32_t a3,
                                         uint32_t b0, uint32_t b1) {
    asm volatile("mma.sync.aligned.m16n8k16.row.col.f32.f16.f16.f32 "
                 "{%0,%1,%2,%3}, {%4,%5,%6,%7}, {%8,%9}, {%0,%1,%2,%3};"
                 : "+f"(c[0]), "+f"(c[1]), "+f"(c[2]), "+f"(c[3])
                 : "r"(a0), "r"(a1), "r"(a2), "r"(a3), "r"(b0), "r"(b1));
}

// ---------------- prep kernels ----------------
__device__ __forceinline__ unsigned pack2(float a, float b) {
    __half2 h = __floats2half2_rn(a, b);
    return *reinterpret_cast<unsigned*>(&h);
}

// one block per input row: fp32 -> fp16 + rowsum (for the zero-point term)
__global__ void __launch_bounds__(128) k_prep_input(const float* __restrict__ x) {
    int row = blockIdx.x;
    const float4* src = reinterpret_cast<const float4*>(x + (size_t)row * K_TOT);
    uint2* dst = reinterpret_cast<uint2*>(g_Xh + (size_t)row * K_TOT);
    float sum = 0.f;
#pragma unroll
    for (int i = 0; i < 8; i++) {
        int idx = threadIdx.x + i * 128;
        float4 v = src[idx];
        sum += (v.x + v.y) + (v.z + v.w);
        uint2 u;
        u.x = pack2(v.x, v.y);
        u.y = pack2(v.z, v.w);
        dst[idx] = u;
    }
#pragma unroll
    for (int o = 16; o; o >>= 1) sum += __shfl_xor_sync(0xFFFFFFFFu, sum, o);
    __shared__ float ws[4];
    if ((threadIdx.x & 31) == 0) ws[threadIdx.x >> 5] = sum;
    __syncthreads();
    if (threadIdx.x == 0) g_rowsum[row] = (ws[0] + ws[1]) + (ws[2] + ws[3]);
}

// int32 (int8-valued) -> fp16, exact
__global__ void __launch_bounds__(256) k_prep_weight(const int* __restrict__ w) {
    size_t i = ((size_t)blockIdx.x * 256 + threadIdx.x) * 4;
    int4 v = *reinterpret_cast<const int4*>(w + i);
    uint2 u;
    u.x = pack2((float)v.x, (float)v.y);
    u.y = pack2((float)v.z, (float)v.w);
    *reinterpret_cast<uint2*>(g_Wh + i) = u;
}

// ---------------- GEMM ----------------
__global__ void __launch_bounds__(THREADS, 2)
k_gemm(const float* __restrict__ scale, const float* __restrict__ zp,
       const float* __restrict__ bias, float* __restrict__ out) {
    extern __shared__ __align__(128) char sm[];
    const uint32_t sbase = smem_u32(sm);

    float* shs = reinterpret_cast<float*>(sm + OFF_PARAM);   // scale       [BN]
    float* shz = shs + BN;                                   // scale*zp    [BN]
    float* shb = shz + BN;                                   // bias        [BN]
    float* srs = shb + BN;                                   // rowsum      [BM]

    const int tid = threadIdx.x;
    const int lane = tid & 31;
    const int wid = tid >> 5;
    const int wm = wid & 1;          // 2 warps along M (64 rows each)
    const int wn = wid >> 1;         // 4 warps along N (32 cols each)
    const int mbase = blockIdx.y * BM;
    const int nbase = blockIdx.x * BN;

    // epilogue params -> smem
    if (tid < BN) {
        int o = nbase + tid;
        float s = scale[o];
        shs[tid] = s;
        shz[tid] = s * zp[o];
        shb[tid] = bias[o];
    }
    if (tid < BM) srs[tid] = g_rowsum[mbase + tid];

    const __half* Ag = g_Xh + (size_t)mbase * K_TOT;
    const __half* Bg = g_Wh + (size_t)nbase * K_TOT;

    // stage loader: A = 1024 16B-chunks (4/thread), B = 1024 (4/thread)
    auto load_stage = [&](int slot, int it) {
        const int kg = it * BK;
        const uint32_t sA = sbase + slot * STG_BYTES;
        const uint32_t sB = sA + A_STAGE_H * 2;
#pragma unroll
        for (int i = 0; i < 4; i++) {
            int q = tid + i * THREADS;
            int row = q >> 3, c = q & 7;
            cp16(sA + row * (BKP * 2) + c * 16, Ag + (size_t)row * K_TOT + kg + c * 8);
        }
#pragma unroll
        for (int i = 0; i < 4; i++) {
            int q = tid + i * THREADS;
            int row = q >> 3, c = q & 7;
            cp16(sB + row * (BKP * 2) + c * 16, Bg + (size_t)row * K_TOT + kg + c * 8);
        }
    };

    float acc[4][4][4];
#pragma unroll
    for (int mt = 0; mt < 4; mt++)
#pragma unroll
        for (int nt = 0; nt < 4; nt++)
#pragma unroll
            for (int r = 0; r < 4; r++) acc[mt][nt][r] = 0.f;

    // base ldmatrix addresses (ks advances by adding 32 bytes)
    const int a_row = wm * 64 + (lane & 15);
    const int a_colb = (lane >> 4) * 16;                       // bytes
    const int b_row = wn * 32 + ((lane >> 4) & 1) * 8 + (lane & 7);
    const int b_colb = ((lane >> 3) & 1) * 16;                 // bytes

    uint32_t af[4][4];
    uint32_t bf[4][2];

    auto load_frags = [&](uint32_t sA, uint32_t sB, int ks) {
        const int kb = ks * 32;    // 16 halves = 32 bytes per ks step
#pragma unroll
        for (int mt = 0; mt < 4; mt++) {
            ldsm4(af[mt][0], af[mt][1], af[mt][2], af[mt][3],
                  sA + (a_row + mt * 16) * (BKP * 2) + a_colb + kb);
        }
#pragma unroll
        for (int np = 0; np < 2; np++) {
            uint32_t r0, r1, r2, r3;
            ldsm4(r0, r1, r2, r3, sB + (b_row + np * 16) * (BKP * 2) + b_colb + kb);
            bf[np * 2 + 0][0] = r0; bf[np * 2 + 0][1] = r1;
            bf[np * 2 + 1][0] = r2; bf[np * 2 + 1][1] = r3;
        }
    };

    auto compute = [&]() {
#pragma unroll
        for (int mt = 0; mt < 4; mt++)
#pragma unroll
            for (int nt = 0; nt < 4; nt++)
                mma16816(acc[mt][nt], af[mt][0], af[mt][1], af[mt][2], af[mt][3],
                         bf[nt][0], bf[nt][1]);
    };

    // prologue: fill stages 0 and 1  (R7-verified ordering: wait -> sync -> prefetch)
    load_stage(0, 0); cp_commit();
    load_stage(1, 1); cp_commit();

    for (int it = 0; it < NIT; ++it) {
        CP_WAIT_GROUP(1);        // my copies of stage `it` done (groups in-order)
        __syncthreads();         // publish all threads' stage-`it` data; slot of it-1 free

        int nx = it + 2;
        if (nx < NIT) load_stage(nx % STAGES, nx);
        cp_commit();             // uniform group accounting (possibly empty group)

        const int slot = it % STAGES;
        const uint32_t sA = sbase + slot * STG_BYTES;
        const uint32_t sB = sA + A_STAGE_H * 2;

#pragma unroll
        for (int ks = 0; ks < 4; ks++) {   // K=64 halves per stage
            load_frags(sA, sB, ks);
            compute();
        }
    }

    // epilogue: fused dequant affine, fp32 out
#pragma unroll
    for (int mt = 0; mt < 4; mt++) {
        const int mrow = wm * 64 + mt * 16 + (lane >> 2);
        const float rs_lo = srs[mrow];
        const float rs_hi = srs[mrow + 8];
        float* p_lo = out + (size_t)(mbase + mrow) * N_TOT + nbase;
        float* p_hi = p_lo + (size_t)8 * N_TOT;
#pragma unroll
        for (int nt = 0; nt < 4; nt++) {
            const int nidx = wn * 32 + nt * 8 + (lane & 3) * 2;
            const float s0 = shs[nidx],     s1 = shs[nidx + 1];
            const float z0 = shz[nidx],     z1 = shz[nidx + 1];
            const float b0 = shb[nidx],     b1 = shb[nidx + 1];
            float2 v0, v1;
            v0.x = fmaf(s0, acc[mt][nt][0], fmaf(-z0, rs_lo, b0));
            v0.y = fmaf(s1, acc[mt][nt][1], fmaf(-z1, rs_lo, b1));
            v1.x = fmaf(s0, acc[mt][nt][2], fmaf(-z0, rs_hi, b0));
            v1.y = fmaf(s1, acc[mt][nt][3], fmaf(-z1, rs_hi, b1));
            *reinterpret_cast<float2*>(p_lo + nidx) = v0;
            *reinterpret_cast<float2*>(p_hi + nidx) = v1;
        }
    }
}

// ---------------- launch ----------------
extern "C" void kernel_launch(void* const* d_in, const int* in_sizes, int n_in,
                              void* d_out, int out_size) {
    const float* x     = (const float*)d_in[0];   // [4,2048,4096] f32
    const int*   w     = (const int*)d_in[1];     // [4096,4096] int32 (int8-valued)
    const float* scale = (const float*)d_in[2];   // [4096]
    const float* zp    = (const float*)d_in[3];   // [4096]
    const float* bias  = (const float*)d_in[4];   // [4096]
    float* out = (float*)d_out;                   // [4,2048,4096] f32

    k_prep_input<<<M_TOT, 128>>>(x);
    k_prep_weight<<<(int)((size_t)N_TOT * K_TOT / (256 * 4)), 256>>>(w);

    cudaFuncSetAttribute(k_gemm, cudaFuncAttributeMaxDynamicSharedMemorySize, DYN_SMEM);
    dim3 grid(N_TOT / BN, M_TOT / BM);   // (32, 64) = 2048 CTAs, 2/SM
    k_gemm<<<grid, THREADS, DYN_SMEM>>>(scale, zp, bias, out);
}

// round 12
// speedup vs baseline: 1.4647x; 1.4647x over previous
#include <cuda_runtime.h>
#include <cuda_fp16.h>
#include <cstdint>

// ---------------- problem constants ----------------
#define M_TOT 8192        // B*S = 4*2048
#define N_TOT 4096        // OUT
#define K_TOT 4096        // IN

// ---------------- GEMM tiling (R9 proven config: classic HMMA, sm_103 baseline) ----
#define BM 128
#define BN 256
#define BK 128                   // K halves per stage (256 B of K per row)
#define BKP 136                  // padded row stride in halves (272 B) — conflict-free ldmatrix
#define STAGES 2
#define NIT (K_TOT / BK)         // 32 main-loop iterations
#define THREADS 512              // 16 warps: 4 (M) x 4 (N), warp tile 32x64

#define A_STAGE_H (BM * BKP)     // 17408 halves
#define B_STAGE_H (BN * BKP)     // 34816 halves
#define STG_BYTES ((A_STAGE_H + B_STAGE_H) * 2)   // 104448 B per stage
#define OFF_PARAM (STAGES * STG_BYTES)            // 208896
#define DYN_SMEM (OFF_PARAM + 3 * BN * 4 + BM * 4)  // 212480 (< 227KB carveout)

// ---------------- scratch (device globals: no allocation allowed) ----------------
__device__ __half g_Xh[(size_t)M_TOT * K_TOT];   // 64 MB fp16 input
__device__ __half g_Wh[(size_t)N_TOT * K_TOT];   // 32 MB fp16 weight (exact int8)
__device__ float  g_rowsum[M_TOT];

// ---------------- PTX helpers (sm_80-era, valid on sm_103 baseline) --------
__device__ __forceinline__ uint32_t smem_u32(const void* p) {
    uint32_t a;
    asm("{ .reg .u64 t; cvta.to.shared.u64 t, %1; cvt.u32.u64 %0, t; }" : "=r"(a) : "l"(p));
    return a;
}

__device__ __forceinline__ void cp16(uint32_t dst, const void* src) {
    asm volatile("cp.async.cg.shared.global [%0], [%1], 16;" :: "r"(dst), "l"(src));
}
__device__ __forceinline__ void cp_commit() {
    asm volatile("cp.async.commit_group;" ::: "memory");
}
#define CP_WAIT_GROUP(n) asm volatile("cp.async.wait_group %0;" :: "n"(n) : "memory")

__device__ __forceinline__ void ldsm4(uint32_t& r0, uint32_t& r1, uint32_t& r2, uint32_t& r3,
                                      uint32_t addr) {
    asm volatile("ldmatrix.sync.aligned.m8n8.x4.shared.b16 {%0,%1,%2,%3}, [%4];"
                 : "=r"(r0), "=r"(r1), "=r"(r2), "=r"(r3) : "r"(addr));
}

__device__ __forceinline__ void mma16816(float* c,
                                         uint32_t a0, uint32_t a1, uint32_t a2, uint32_t a3,
                                         uint32_t b0, uint32_t b1) {
    asm volatile("mma.sync.aligned.m16n8k16.row.col.f32.f16.f16.f32 "
                 "{%0,%1,%2,%3}, {%4,%5,%6,%7}, {%8,%9}, {%0,%1,%2,%3};"
                 : "+f"(c[0]), "+f"(c[1]), "+f"(c[2]), "+f"(c[3])
                 : "r"(a0), "r"(a1), "r"(a2), "r"(a3), "r"(b0), "r"(b1));
}

// ---------------- fused prep kernel ----------------
__device__ __forceinline__ unsigned pack2(float a, float b) {
    __half2 h = __floats2half2_rn(a, b);
    return *reinterpret_cast<unsigned*>(&h);
}

// blocks [0, M_TOT): one input row each (fp32 -> fp16 + rowsum)
// blocks [M_TOT, M_TOT + W_BLOCKS): weight int32 -> fp16, 512 elems per block
#define W_BLOCKS ((int)((size_t)N_TOT * K_TOT / (128 * 4)))   // 32768

__global__ void __launch_bounds__(128) k_prep(const float* __restrict__ x,
                                              const int* __restrict__ w) {
    if (blockIdx.x < M_TOT) {
        int row = blockIdx.x;
        const float4* src = reinterpret_cast<const float4*>(x + (size_t)row * K_TOT);
        uint2* dst = reinterpret_cast<uint2*>(g_Xh + (size_t)row * K_TOT);
        float sum = 0.f;
#pragma unroll
        for (int i = 0; i < 8; i++) {
            int idx = threadIdx.x + i * 128;
            float4 v = src[idx];
            sum += (v.x + v.y) + (v.z + v.w);
            uint2 u;
            u.x = pack2(v.x, v.y);
            u.y = pack2(v.z, v.w);
            dst[idx] = u;
        }
#pragma unroll
        for (int o = 16; o; o >>= 1) sum += __shfl_xor_sync(0xFFFFFFFFu, sum, o);
        __shared__ float ws[4];
        if ((threadIdx.x & 31) == 0) ws[threadIdx.x >> 5] = sum;
        __syncthreads();
        if (threadIdx.x == 0) g_rowsum[row] = (ws[0] + ws[1]) + (ws[2] + ws[3]);
    } else {
        size_t i = (((size_t)(blockIdx.x - M_TOT) * 128 + threadIdx.x)) * 4;
        int4 v = *reinterpret_cast<const int4*>(w + i);
        uint2 u;
        u.x = pack2((float)v.x, (float)v.y);
        u.y = pack2((float)v.z, (float)v.w);
        *reinterpret_cast<uint2*>(g_Wh + i) = u;
    }
}

// ---------------- GEMM (R9 proven) ----------------
__global__ void __launch_bounds__(THREADS, 1)
k_gemm(const float* __restrict__ scale, const float* __restrict__ zp,
       const float* __restrict__ bias, float* __restrict__ out) {
    extern __shared__ __align__(128) char sm[];
    const uint32_t sbase = smem_u32(sm);

    float* shs = reinterpret_cast<float*>(sm + OFF_PARAM);   // scale       [BN]
    float* shz = shs + BN;                                   // scale*zp    [BN]
    float* shb = shz + BN;                                   // bias        [BN]
    float* srs = shb + BN;                                   // rowsum      [BM]

    const int tid = threadIdx.x;
    const int lane = tid & 31;
    const int wid = tid >> 5;
    const int wm = wid & 3;          // 4 warps along M (32 rows each)
    const int wn = wid >> 2;         // 4 warps along N (64 cols each)
    const int mbase = blockIdx.y * BM;
    const int nbase = blockIdx.x * BN;

    // epilogue params -> smem
    for (int i = tid; i < BN; i += THREADS) {
        int o = nbase + i;
        float s = scale[o];
        shs[i] = s;
        shz[i] = s * zp[o];
        shb[i] = bias[o];
    }
    if (tid < BM) srs[tid] = g_rowsum[mbase + tid];

    const __half* Ag = g_Xh + (size_t)mbase * K_TOT;
    const __half* Bg = g_Wh + (size_t)nbase * K_TOT;

    // stage loader: A = 2048 16B-chunks (4/thread), B = 4096 (8/thread)
    auto load_stage = [&](int slot, int it) {
        const int kg = it * BK;
        const uint32_t sA = sbase + slot * STG_BYTES;
        const uint32_t sB = sA + A_STAGE_H * 2;
#pragma unroll
        for (int i = 0; i < 4; i++) {
            int q = tid + i * THREADS;
            int row = q >> 4, c = q & 15;
            cp16(sA + row * (BKP * 2) + c * 16, Ag + (size_t)row * K_TOT + kg + c * 8);
        }
#pragma unroll
        for (int i = 0; i < 8; i++) {
            int q = tid + i * THREADS;
            int row = q >> 4, c = q & 15;
            cp16(sB + row * (BKP * 2) + c * 16, Bg + (size_t)row * K_TOT + kg + c * 8);
        }
    };

    float acc[2][8][4];
#pragma unroll
    for (int mt = 0; mt < 2; mt++)
#pragma unroll
        for (int nt = 0; nt < 8; nt++)
#pragma unroll
            for (int r = 0; r < 4; r++) acc[mt][nt][r] = 0.f;

    // base ldmatrix addresses (ks advances by adding 32 bytes)
    const int a_row = wm * 32 + (lane & 15);
    const int a_colb = (lane >> 4) * 16;                       // bytes
    const int b_row = wn * 64 + ((lane >> 4) & 1) * 8 + (lane & 7);
    const int b_colb = ((lane >> 3) & 1) * 16;                 // bytes

    uint32_t af[2][2][4];
    uint32_t bf[2][8][2];

    auto load_frags = [&](uint32_t sA, uint32_t sB, int ks, int buf) {
        const int kb = ks * 32;    // 16 halves = 32 bytes per ks step
#pragma unroll
        for (int mt = 0; mt < 2; mt++) {
            ldsm4(af[buf][mt][0], af[buf][mt][1], af[buf][mt][2], af[buf][mt][3],
                  sA + (a_row + mt * 16) * (BKP * 2) + a_colb + kb);
        }
#pragma unroll
        for (int np = 0; np < 4; np++) {
            uint32_t r0, r1, r2, r3;
            ldsm4(r0, r1, r2, r3, sB + (b_row + np * 16) * (BKP * 2) + b_colb + kb);
            bf[buf][np * 2 + 0][0] = r0; bf[buf][np * 2 + 0][1] = r1;
            bf[buf][np * 2 + 1][0] = r2; bf[buf][np * 2 + 1][1] = r3;
        }
    };

    auto compute = [&](int buf) {
#pragma unroll
        for (int mt = 0; mt < 2; mt++)
#pragma unroll
            for (int nt = 0; nt < 8; nt++)
                mma16816(acc[mt][nt], af[buf][mt][0], af[buf][mt][1],
                         af[buf][mt][2], af[buf][mt][3],
                         bf[buf][nt][0], bf[buf][nt][1]);
    };

    // prologue: fill stage 0
    load_stage(0, 0); cp_commit();

    for (int it = 0; it < NIT; ++it) {
        // 1) drain my own copies of stage `it` (issued one full iteration ago)
        CP_WAIT_GROUP(0);
        // 2) barrier: publishes ALL threads' stage-`it` data, and confirms every
        //    warp finished computing stage `it-1` (so its slot is reusable)
        __syncthreads();
        // 3) prefetch stage `it+1` into the freed slot; streams during compute
        if (it + 1 < NIT) {
            load_stage((it + 1) & 1, it + 1);
            cp_commit();
        }

        const uint32_t sA = sbase + (it & 1) * STG_BYTES;
        const uint32_t sB = sA + A_STAGE_H * 2;

        // software-pipelined fragment loop over 8 ks steps (K=128 halves)
        load_frags(sA, sB, 0, 0);
#pragma unroll
        for (int ks = 0; ks < 8; ks++) {
            if (ks < 7) load_frags(sA, sB, ks + 1, (ks + 1) & 1);
            compute(ks & 1);
        }
    }

    // epilogue: fused dequant affine, fp32 out
#pragma unroll
    for (int mt = 0; mt < 2; mt++) {
        const int mrow = wm * 32 + mt * 16 + (lane >> 2);
        const float rs_lo = srs[mrow];
        const float rs_hi = srs[mrow + 8];
        float* p_lo = out + (size_t)(mbase + mrow) * N_TOT + nbase;
        float* p_hi = p_lo + (size_t)8 * N_TOT;
#pragma unroll
        for (int nt = 0; nt < 8; nt++) {
            const int nidx = wn * 64 + nt * 8 + (lane & 3) * 2;
            const float s0 = shs[nidx],     s1 = shs[nidx + 1];
            const float z0 = shz[nidx],     z1 = shz[nidx + 1];
            const float b0 = shb[nidx],     b1 = shb[nidx + 1];
            float2 v0, v1;
            v0.x = fmaf(s0, acc[mt][nt][0], fmaf(-z0, rs_lo, b0));
            v0.y = fmaf(s1, acc[mt][nt][1], fmaf(-z1, rs_lo, b1));
            v1.x = fmaf(s0, acc[mt][nt][2], fmaf(-z0, rs_hi, b0));
            v1.y = fmaf(s1, acc[mt][nt][3], fmaf(-z1, rs_hi, b1));
            *reinterpret_cast<float2*>(p_lo + nidx) = v0;
            *reinterpret_cast<float2*>(p_hi + nidx) = v1;
        }
    }
}

// ---------------- launch ----------------
extern "C" void kernel_launch(void* const* d_in, const int* in_sizes, int n_in,
                              void* d_out, int out_size) {
    const float* x     = (const float*)d_in[0];   // [4,2048,4096] f32
    const int*   w     = (const int*)d_in[1];     // [4096,4096] int32 (int8-valued)
    const float* scale = (const float*)d_in[2];   // [4096]
    const float* zp    = (const float*)d_in[3];   // [4096]
    const float* bias  = (const float*)d_in[4];   // [4096]
    float* out = (float*)d_out;                   // [4,2048,4096] f32

    k_prep<<<M_TOT + W_BLOCKS, 128>>>(x, w);      // fused input+weight prep

    cudaFuncSetAttribute(k_gemm, cudaFuncAttributeMaxDynamicSharedMemorySize, DYN_SMEM);
    dim3 grid(N_TOT / BN, M_TOT / BM);   // (16, 64)
    k_gemm<<<grid, THREADS, DYN_SMEM>>>(scale, zp, bias, out);
}

// round 13
// speedup vs baseline: 1.5269x; 1.0425x over previous
#include <cuda_runtime.h>
#include <cuda_fp16.h>
#include <cstdint>

// ---------------- problem constants ----------------
#define M_TOT 8192        // B*S = 4*2048
#define N_TOT 4096        // OUT
#define K_TOT 4096        // IN

// ---------------- GEMM tiling: 2 CTAs/SM, two independent barrier domains ----
#define BM 128
#define BN 128
#define BK 64                    // K halves per stage (128 B of K per row)
#define BKP 72                   // padded row stride in halves (144 B) — conflict-free ldmatrix
#define STAGES 2
#define NIT (K_TOT / BK)         // 64 main-loop iterations
#define THREADS 256              // 8 warps: 2 (M) x 4 (N), warp tile 64x32

#define A_STAGE_H (BM * BKP)     // 9216 halves
#define B_STAGE_H (BN * BKP)     // 9216 halves
#define STG_BYTES ((A_STAGE_H + B_STAGE_H) * 2)   // 36864 B per stage
#define OFF_PARAM (STAGES * STG_BYTES)            // 73728
#define DYN_SMEM (OFF_PARAM + 3 * BN * 4 + BM * 4)  // 75776 -> 2 CTAs = 151.5KB/SM

// ---------------- scratch (device globals: no allocation allowed) ----------------
__device__ __half g_Xh[(size_t)M_TOT * K_TOT];   // 64 MB fp16 input
__device__ __half g_Wh[(size_t)N_TOT * K_TOT];   // 32 MB fp16 weight (exact int8)
__device__ float  g_rowsum[M_TOT];

// ---------------- PTX helpers (sm_80-era, valid on sm_103 baseline) --------
__device__ __forceinline__ uint32_t smem_u32(const void* p) {
    uint32_t a;
    asm("{ .reg .u64 t; cvta.to.shared.u64 t, %1; cvt.u32.u64 %0, t; }" : "=r"(a) : "l"(p));
    return a;
}

__device__ __forceinline__ void cp16(uint32_t dst, const void* src) {
    asm volatile("cp.async.cg.shared.global [%0], [%1], 16;" :: "r"(dst), "l"(src));
}
__device__ __forceinline__ void cp_commit() {
    asm volatile("cp.async.commit_group;" ::: "memory");
}
#define CP_WAIT_GROUP(n) asm volatile("cp.async.wait_group %0;" :: "n"(n) : "memory")

__device__ __forceinline__ void ldsm4(uint32_t& r0, uint32_t& r1, uint32_t& r2, uint32_t& r3,
                                      uint32_t addr) {
    asm volatile("ldmatrix.sync.aligned.m8n8.x4.shared.b16 {%0,%1,%2,%3}, [%4];"
                 : "=r"(r0), "=r"(r1), "=r"(r2), "=r"(r3) : "r"(addr));
}

__device__ __forceinline__ void mma16816(float* c,
                                         uint32_t a0, uint32_t a1, uint32_t a2, uint32_t a3,
                                         uint32_t b0, uint32_t b1) {
    asm volatile("mma.sync.aligned.m16n8k16.row.col.f32.f16.f16.f32 "
                 "{%0,%1,%2,%3}, {%4,%5,%6,%7}, {%8,%9}, {%0,%1,%2,%3};"
                 : "+f"(c[0]), "+f"(c[1]), "+f"(c[2]), "+f"(c[3])
                 : "r"(a0), "r"(a1), "r"(a2), "r"(a3), "r"(b0), "r"(b1));
}

// ---------------- fused prep kernel ----------------
__device__ __forceinline__ unsigned pack2(float a, float b) {
    __half2 h = __floats2half2_rn(a, b);
    return *reinterpret_cast<unsigned*>(&h);
}

#define W_BLOCKS ((int)((size_t)N_TOT * K_TOT / (128 * 4)))   // 32768

__global__ void __launch_bounds__(128) k_prep(const float* __restrict__ x,
                                              const int* __restrict__ w) {
    if (blockIdx.x < M_TOT) {
        int row = blockIdx.x;
        const float4* src = reinterpret_cast<const float4*>(x + (size_t)row * K_TOT);
        uint2* dst = reinterpret_cast<uint2*>(g_Xh + (size_t)row * K_TOT);
        float sum = 0.f;
#pragma unroll
        for (int i = 0; i < 8; i++) {
            int idx = threadIdx.x + i * 128;
            float4 v = src[idx];
            sum += (v.x + v.y) + (v.z + v.w);
            uint2 u;
            u.x = pack2(v.x, v.y);
            u.y = pack2(v.z, v.w);
            dst[idx] = u;
        }
#pragma unroll
        for (int o = 16; o; o >>= 1) sum += __shfl_xor_sync(0xFFFFFFFFu, sum, o);
        __shared__ float ws[4];
        if ((threadIdx.x & 31) == 0) ws[threadIdx.x >> 5] = sum;
        __syncthreads();
        if (threadIdx.x == 0) g_rowsum[row] = (ws[0] + ws[1]) + (ws[2] + ws[3]);
    } else {
        size_t i = (((size_t)(blockIdx.x - M_TOT) * 128 + threadIdx.x)) * 4;
        int4 v = *reinterpret_cast<const int4*>(w + i);
        uint2 u;
        u.x = pack2((float)v.x, (float)v.y);
        u.y = pack2((float)v.z, (float)v.w);
        *reinterpret_cast<uint2*>(g_Wh + i) = u;
    }
}

// ---------------- GEMM ----------------
__global__ void __launch_bounds__(THREADS, 2)
k_gemm(const float* __restrict__ scale, const float* __restrict__ zp,
       const float* __restrict__ bias, float* __restrict__ out) {
    extern __shared__ __align__(128) char sm[];
    const uint32_t sbase = smem_u32(sm);

    float* shs = reinterpret_cast<float*>(sm + OFF_PARAM);   // scale       [BN]
    float* shz = shs + BN;                                   // scale*zp    [BN]
    float* shb = shz + BN;                                   // bias        [BN]
    float* srs = shb + BN;                                   // rowsum      [BM]

    const int tid = threadIdx.x;
    const int lane = tid & 31;
    const int wid = tid >> 5;
    const int wm = wid & 1;          // 2 warps along M (64 rows each)
    const int wn = wid >> 1;         // 4 warps along N (32 cols each)
    const int mbase = blockIdx.y * BM;
    const int nbase = blockIdx.x * BN;

    // epilogue params -> smem
    if (tid < BN) {
        int o = nbase + tid;
        float s = scale[o];
        shs[tid] = s;
        shz[tid] = s * zp[o];
        shb[tid] = bias[o];
    }
    if (tid < BM) srs[tid] = g_rowsum[mbase + tid];

    const __half* Ag = g_Xh + (size_t)mbase * K_TOT;
    const __half* Bg = g_Wh + (size_t)nbase * K_TOT;

    // stage loader: A = 1024 16B-chunks (4/thread), B = 1024 (4/thread)
    auto load_stage = [&](int slot, int it) {
        const int kg = it * BK;
        const uint32_t sA = sbase + slot * STG_BYTES;
        const uint32_t sB = sA + A_STAGE_H * 2;
#pragma unroll
        for (int i = 0; i < 4; i++) {
            int q = tid + i * THREADS;
            int row = q >> 3, c = q & 7;
            cp16(sA + row * (BKP * 2) + c * 16, Ag + (size_t)row * K_TOT + kg + c * 8);
        }
#pragma unroll
        for (int i = 0; i < 4; i++) {
            int q = tid + i * THREADS;
            int row = q >> 3, c = q & 7;
            cp16(sB + row * (BKP * 2) + c * 16, Bg + (size_t)row * K_TOT + kg + c * 8);
        }
    };

    float acc[4][4][4];
#pragma unroll
    for (int mt = 0; mt < 4; mt++)
#pragma unroll
        for (int nt = 0; nt < 4; nt++)
#pragma unroll
            for (int r = 0; r < 4; r++) acc[mt][nt][r] = 0.f;

    // base ldmatrix addresses (ks advances by adding 32 bytes)
    const int a_row = wm * 64 + (lane & 15);
    const int a_colb = (lane >> 4) * 16;                       // bytes
    const int b_row = wn * 32 + ((lane >> 4) & 1) * 8 + (lane & 7);
    const int b_colb = ((lane >> 3) & 1) * 16;                 // bytes

    uint32_t af[2][4][4];
    uint32_t bf[2][4][2];

    auto load_frags = [&](uint32_t sA, uint32_t sB, int ks, int buf) {
        const int kb = ks * 32;    // 16 halves = 32 bytes per ks step
#pragma unroll
        for (int mt = 0; mt < 4; mt++) {
            ldsm4(af[buf][mt][0], af[buf][mt][1], af[buf][mt][2], af[buf][mt][3],
                  sA + (a_row + mt * 16) * (BKP * 2) + a_colb + kb);
        }
#pragma unroll
        for (int np = 0; np < 2; np++) {
            uint32_t r0, r1, r2, r3;
            ldsm4(r0, r1, r2, r3, sB + (b_row + np * 16) * (BKP * 2) + b_colb + kb);
            bf[buf][np * 2 + 0][0] = r0; bf[buf][np * 2 + 0][1] = r1;
            bf[buf][np * 2 + 1][0] = r2; bf[buf][np * 2 + 1][1] = r3;
        }
    };

    auto compute = [&](int buf) {
#pragma unroll
        for (int mt = 0; mt < 4; mt++)
#pragma unroll
            for (int nt = 0; nt < 4; nt++)
                mma16816(acc[mt][nt], af[buf][mt][0], af[buf][mt][1],
                         af[buf][mt][2], af[buf][mt][3],
                         bf[buf][nt][0], bf[buf][nt][1]);
    };

    // prologue: fill stage 0
    load_stage(0, 0); cp_commit();

    for (int it = 0; it < NIT; ++it) {
        // 1) drain my own copies of stage `it` (issued one full iteration ago)
        CP_WAIT_GROUP(0);
        // 2) barrier: publishes ALL threads' stage-`it` data; slot of it-1 reusable
        __syncthreads();
        // 3) prefetch stage `it+1` into the freed slot; streams during compute
        if (it + 1 < NIT) {
            load_stage((it + 1) & 1, it + 1);
            cp_commit();
        }

        const uint32_t sA = sbase + (it & 1) * STG_BYTES;
        const uint32_t sB = sA + A_STAGE_H * 2;

        // software-pipelined fragment loop over 4 ks steps (K=64 halves)
        load_frags(sA, sB, 0, 0);
#pragma unroll
        for (int ks = 0; ks < 4; ks++) {
            if (ks < 3) load_frags(sA, sB, ks + 1, (ks + 1) & 1);
            compute(ks & 1);
        }
    }

    // epilogue: fused dequant affine, fp32 out
#pragma unroll
    for (int mt = 0; mt < 4; mt++) {
        const int mrow = wm * 64 + mt * 16 + (lane >> 2);
        const float rs_lo = srs[mrow];
        const float rs_hi = srs[mrow + 8];
        float* p_lo = out + (size_t)(mbase + mrow) * N_TOT + nbase;
        float* p_hi = p_lo + (size_t)8 * N_TOT;
#pragma unroll
        for (int nt = 0; nt < 4; nt++) {
            const int nidx = wn * 32 + nt * 8 + (lane & 3) * 2;
            const float s0 = shs[nidx],     s1 = shs[nidx + 1];
            const float z0 = shz[nidx],     z1 = shz[nidx + 1];
            const float b0 = shb[nidx],     b1 = shb[nidx + 1];
            float2 v0, v1;
            v0.x = fmaf(s0, acc[mt][nt][0], fmaf(-z0, rs_lo, b0));
            v0.y = fmaf(s1, acc[mt][nt][1], fmaf(-z1, rs_lo, b1));
            v1.x = fmaf(s0, acc[mt][nt][2], fmaf(-z0, rs_hi, b0));
            v1.y = fmaf(s1, acc[mt][nt][3], fmaf(-z1, rs_hi, b1));
            *reinterpret_cast<float2*>(p_lo + nidx) = v0;
            *reinterpret_cast<float2*>(p_hi + nidx) = v1;
        }
    }
}

// ---------------- launch ----------------
extern "C" void kernel_launch(void* const* d_in, const int* in_sizes, int n_in,
                              void* d_out, int out_size) {
    const float* x     = (const float*)d_in[0];   // [4,2048,4096] f32
    const int*   w     = (const int*)d_in[1];     // [4096,4096] int32 (int8-valued)
    const float* scale = (const float*)d_in[2];   // [4096]
    const float* zp    = (const float*)d_in[3];   // [4096]
    const float* bias  = (const float*)d_in[4];   // [4096]
    float* out = (float*)d_out;                   // [4,2048,4096] f32

    k_prep<<<M_TOT + W_BLOCKS, 128>>>(x, w);      // fused input+weight prep

    cudaFuncSetAttribute(k_gemm, cudaFuncAttributeMaxDynamicSharedMemorySize, DYN_SMEM);
    dim3 grid(N_TOT / BN, M_TOT / BM);   // (32, 64) = 2048 CTAs, 2/SM
    k_gemm<<<grid, THREADS, DYN_SMEM>>>(scale, zp, bias, out);
}